// round 17
// baseline (speedup 1.0000x reference)
#include <cuda_runtime.h>
#include <cstdint>
#include <mma.h>

using namespace nvcuda;

#define B_   256
#define T_   2048
#define IN_  128
#define H_   64
#define G_   256   // 4*H
#define PIT  20    // smem pitch (floats): 80 B, 16B-aligned, conflict-breaking

// Scratch (allocation-free rule: static __device__ array)
__device__ float g_xp[(size_t)B_ * T_ * G_];   // x@W_ih1^T (NO bias — folded in lstm)

typedef unsigned long long u64;

// ---------------- helpers ----------------
__device__ __forceinline__ void ffma2(u64& d, u64 a, u64 b) {
    asm("fma.rn.f32x2 %0, %1, %2, %0;" : "+l"(d) : "l"(a), "l"(b));
}
__device__ __forceinline__ float2 unpk(u64 p) {
    float2 r;
    asm("mov.b64 {%0, %1}, %2;" : "=f"(r.x), "=f"(r.y) : "l"(p));
    return r;
}
__device__ __forceinline__ float tanh_hw(float x) {
    float r;
    asm("tanh.approx.f32 %0, %1;" : "=f"(r) : "f"(x));
    return r;
}
__device__ __forceinline__ float sig_hw(float x) {
    return fmaf(0.5f, tanh_hw(0.5f * x), 0.5f);
}

// ---------------- kernel 1: xp = x @ W_ih1^T  (tf32 wmma, pipelined staging) ----------------
// M = B*T, N = 256, K = 128. 4096 blocks x 256 thr (8 warps).
// BM=128 (4 m-warps x 32 rows), BN=256 (2 n-warps x 128 cols).
// k in 16-wide chunks; chunk c+1's gmem loads are issued into REGISTERS before
// chunk c's mma work, so DRAM latency hides under tensor math.
__global__ __launch_bounds__(256) void xp_wmma(const float* __restrict__ x,
                                               const float* __restrict__ W) {
    __shared__ float Xs[128][PIT];
    __shared__ float Ws[256][PIT];
    int tid = threadIdx.x;
    int wid = tid >> 5;
    int mwarp = wid >> 1, nwarp = wid & 1;
    size_t mbase = (size_t)blockIdx.x * 128;
    int mrow = mwarp * 32;
    int nbase = nwarp * 128;

    // per-thread staging coords
    int xr = tid >> 1, xc4 = (tid & 1) << 3;              // 128 rows x 16 f: 2 float4/thr
    const float* xg = x + (mbase + xr) * IN_ + xc4;
    int wr0 = tid >> 1, wc4 = (tid & 1) << 3;             // rows tid>>1 and 128+(tid>>1)
    const float* wg0 = W + (size_t)wr0 * IN_ + wc4;
    const float* wg1 = W + (size_t)(128 + wr0) * IN_ + wc4;

    wmma::fragment<wmma::accumulator, 16, 16, 8, float> acc[2][8];
#pragma unroll
    for (int i = 0; i < 2; i++)
#pragma unroll
        for (int j = 0; j < 8; j++) wmma::fill_fragment(acc[i][j], 0.0f);

    // prologue: stage chunk 0 into regs
    float4 rx0, rx1, rw0, rw1, rw2, rw3;
    rx0 = *(const float4*)(xg + 0);
    rx1 = *(const float4*)(xg + 4);
    rw0 = *(const float4*)(wg0 + 0);
    rw1 = *(const float4*)(wg0 + 4);
    rw2 = *(const float4*)(wg1 + 0);
    rw3 = *(const float4*)(wg1 + 4);

#pragma unroll
    for (int c = 0; c < 8; c++) {
        int k0 = c * 16;
        __syncthreads();   // previous chunk's smem reads done
        *(float4*)&Xs[xr][xc4 + 0] = rx0;
        *(float4*)&Xs[xr][xc4 + 4] = rx1;
        *(float4*)&Ws[wr0][wc4 + 0] = rw0;
        *(float4*)&Ws[wr0][wc4 + 4] = rw1;
        *(float4*)&Ws[128 + wr0][wc4 + 0] = rw2;
        *(float4*)&Ws[128 + wr0][wc4 + 4] = rw3;
        __syncthreads();

        if (c + 1 < 8) {   // issue next chunk's LDG before the mma work
            int kn = k0 + 16;
            rx0 = *(const float4*)(xg + kn + 0);
            rx1 = *(const float4*)(xg + kn + 4);
            rw0 = *(const float4*)(wg0 + kn + 0);
            rw1 = *(const float4*)(wg0 + kn + 4);
            rw2 = *(const float4*)(wg1 + kn + 0);
            rw3 = *(const float4*)(wg1 + kn + 4);
        }

#pragma unroll
        for (int kk = 0; kk < 16; kk += 8) {
            wmma::fragment<wmma::matrix_a, 16, 16, 8, wmma::precision::tf32,
                           wmma::row_major> af[2];
            wmma::fragment<wmma::matrix_b, 16, 16, 8, wmma::precision::tf32,
                           wmma::col_major> bf[8];
#pragma unroll
            for (int i = 0; i < 2; i++) {
                wmma::load_matrix_sync(af[i], &Xs[mrow + i * 16][kk], PIT);
#pragma unroll
                for (int e = 0; e < af[i].num_elements; e++)
                    af[i].x[e] = wmma::__float_to_tf32(af[i].x[e]);
            }
#pragma unroll
            for (int j = 0; j < 8; j++) {
                wmma::load_matrix_sync(bf[j], &Ws[nbase + j * 16][kk], PIT);
#pragma unroll
                for (int e = 0; e < bf[j].num_elements; e++)
                    bf[j].x[e] = wmma::__float_to_tf32(bf[j].x[e]);
            }
#pragma unroll
            for (int i = 0; i < 2; i++)
#pragma unroll
                for (int j = 0; j < 8; j++)
                    wmma::mma_sync(acc[i][j], af[i], bf[j], acc[i][j]);
        }
    }

#pragma unroll
    for (int i = 0; i < 2; i++)
#pragma unroll
        for (int j = 0; j < 8; j++)
            wmma::store_matrix_sync(
                g_xp + (mbase + mrow + i * 16) * G_ + nbase + j * 16,
                acc[i][j], G_, wmma::mem_row_major);
}

// ---------------- kernel 2: fused 2-layer LSTM recurrence + output head ----------------
// R14/R15 structure; xq prefetch HOISTED to the top of the step (max distance
// to its consumer in reduce-b: cell1 + P2a + B1 + fused pass + reduce-a).
__global__ __launch_bounds__(256, 1) void lstm_rec(
    const float* __restrict__ Whh1, const float* __restrict__ Wih2,
    const float* __restrict__ Whh2, const float* __restrict__ bih1,
    const float* __restrict__ bhh1, const float* __restrict__ bih2,
    const float* __restrict__ bhh2, const float* __restrict__ Wout,
    const float* __restrict__ bout, float* __restrict__ out) {
    __shared__ float h1s[2][2][64];   // [parity][row][unit]
    __shared__ float h2s[2][2][64];
    __shared__ float red[16];         // [warp][row]

    int tid = threadIdx.x;
    int q = tid >> 2, s = tid & 3;
    int myrow = s & 1;
    int prow = myrow ^ 1;

    u64 w1[4][8], w2i[4][8], w2h[4][8];
#pragma unroll
    for (int g = 0; g < 4; g++) {
        const u64* p;
        p = (const u64*)(Whh1 + (size_t)(g * 64 + q) * 64 + s * 16);
#pragma unroll
        for (int j = 0; j < 8; j++) w1[g][j] = p[j];
        p = (const u64*)(Wih2 + (size_t)(g * 64 + q) * 64 + s * 16);
#pragma unroll
        for (int j = 0; j < 8; j++) w2i[g][j] = p[j];
        p = (const u64*)(Whh2 + (size_t)(g * 64 + q) * 64 + s * 16);
#pragma unroll
        for (int j = 0; j < 8; j++) w2h[g][j] = p[j];
    }
    float b1v = bih1[s * 64 + q] + bhh1[s * 64 + q];
    float b2v = bih2[s * 64 + q] + bhh2[s * 64 + q];
    float wo = Wout[q];
    float bo = bout[0];
    float c1 = 0.0f, c2 = 0.0f;

    int b0 = blockIdx.x * 2;
    const float* xprow0 = g_xp + (size_t)b0 * T_ * G_ + s * 64 + q;
    const float* xprow1 = xprow0 + (size_t)T_ * G_;
    const float* xpo = myrow ? xprow1 : xprow0;
    const float* xpp = myrow ? xprow0 : xprow1;
    float xqo = xpo[0];
    float xqp = xpp[0];

    if (tid < 128) {
        h1s[1][tid >> 6][tid & 63] = 0.0f;
        h2s[1][tid >> 6][tid & 63] = 0.0f;
    }
    __syncthreads();

    float wv1[4];
#pragma unroll
    for (int g = 0; g < 4; g++) {
        float fo = (s == g) ? (xqo + b1v) : 0.0f;
        float fp = (s == g) ? (xqp + b1v) : 0.0f;
        float tt = fo + __shfl_xor_sync(0xffffffffu, fp, 1);
        tt += __shfl_xor_sync(0xffffffffu, tt, 2);
        wv1[g] = tt;
    }

    auto step = [&](const int CUR, const int PRV, const int TT) {
        // ---- xq prefetch FIRST: xp(TT+1), consumed in reduce-b below ----
        if (TT + 1 < T_) {
            xpo += G_; xpp += G_;
            xqo = *xpo;
            xqp = *xpp;
        }

        // ---- cell-1 update from carried wv1 -> h1(TT) ----
        float h1v;
        {
            float iv = sig_hw(wv1[0]), fv = sig_hw(wv1[1]);
            float gv = tanh_hw(wv1[2]), ov = sig_hw(wv1[3]);
            c1 = fv * c1 + iv * gv;
            h1v = ov * tanh_hw(c1);
        }

        // ---- P2a: layer-2 dots over h2 PREV ----
        u64 a[8];
#pragma unroll
        for (int i = 0; i < 8; i++) a[i] = 0ull;
        {
            const ulonglong2* hO = (const ulonglong2*)&h2s[PRV][myrow][s * 16];
            const ulonglong2* hP = (const ulonglong2*)&h2s[PRV][prow][s * 16];
#pragma unroll
            for (int j = 0; j < 4; j++) {
                ulonglong2 zo = hO[j];
                ulonglong2 zp = hP[j];
#pragma unroll
                for (int g = 0; g < 4; g++) {
                    ffma2(a[2 * g + 0], w2h[g][2 * j], zo.x);
                    ffma2(a[2 * g + 0], w2h[g][2 * j + 1], zo.y);
                    ffma2(a[2 * g + 1], w2h[g][2 * j], zp.x);
                    ffma2(a[2 * g + 1], w2h[g][2 * j + 1], zp.y);
                }
            }
        }
        if (s < 2) h1s[CUR][s][q] = h1v;
        __syncthreads();                     // B1

        // ---- fused pass over h1 NEW: P2b (into a) + P1(TT+1) (into b) ----
        u64 b[8];
#pragma unroll
        for (int i = 0; i < 8; i++) b[i] = 0ull;
        {
            const ulonglong2* hO = (const ulonglong2*)&h1s[CUR][myrow][s * 16];
            const ulonglong2* hP = (const ulonglong2*)&h1s[CUR][prow][s * 16];
#pragma unroll
            for (int j = 0; j < 4; j++) {
                ulonglong2 uo = hO[j];
                ulonglong2 up = hP[j];
#pragma unroll
                for (int g = 0; g < 4; g++) {
                    ffma2(a[2 * g + 0], w2i[g][2 * j], uo.x);
                    ffma2(a[2 * g + 0], w2i[g][2 * j + 1], uo.y);
                    ffma2(a[2 * g + 1], w2i[g][2 * j], up.x);
                    ffma2(a[2 * g + 1], w2i[g][2 * j + 1], up.y);
                }
#pragma unroll
                for (int g = 0; g < 4; g++) {
                    ffma2(b[2 * g + 0], w1[g][2 * j], uo.x);
                    ffma2(b[2 * g + 0], w1[g][2 * j + 1], uo.y);
                    ffma2(b[2 * g + 1], w1[g][2 * j], up.x);
                    ffma2(b[2 * g + 1], w1[g][2 * j + 1], up.y);
                }
            }
        }

        float wv2[4];
#pragma unroll
        for (int g = 0; g < 4; g++) {
            float bb = (s == g) ? b2v : 0.0f;
            float2 fo = unpk(a[2 * g + 0]);
            float2 fp = unpk(a[2 * g + 1]);
            float vo = fo.x + fo.y + bb;
            float vp = fp.x + fp.y + bb;
            float tt = vo + __shfl_xor_sync(0xffffffffu, vp, 1);
            tt += __shfl_xor_sync(0xffffffffu, tt, 2);
            wv2[g] = tt;
        }

#pragma unroll
        for (int g = 0; g < 4; g++) {
            float2 fo = unpk(b[2 * g + 0]);
            float2 fp = unpk(b[2 * g + 1]);
            float vo = fo.x + fo.y + ((s == g) ? (xqo + b1v) : 0.0f);
            float vp = fp.x + fp.y + ((s == g) ? (xqp + b1v) : 0.0f);
            float tt = vo + __shfl_xor_sync(0xffffffffu, vp, 1);
            tt += __shfl_xor_sync(0xffffffffu, tt, 2);
            wv1[g] = tt;
        }

        {
            float iv = sig_hw(wv2[0]), fv = sig_hw(wv2[1]);
            float gv = tanh_hw(wv2[2]), ov = sig_hw(wv2[3]);
            c2 = fv * c2 + iv * gv;
            float h2v = ov * tanh_hw(c2);
            if (s < 2) h2s[CUR][s][q] = h2v;
            float p = wo * h2v;
            p += __shfl_xor_sync(0xffffffffu, p, 4);
            p += __shfl_xor_sync(0xffffffffu, p, 8);
            p += __shfl_xor_sync(0xffffffffu, p, 16);
            if ((tid & 31) < 2) red[(tid >> 5) * 2 + s] = p;
        }
        __syncthreads();              // B2

        if (tid < 2) {
            float r = bo;
#pragma unroll
            for (int w = 0; w < 8; w++) r += red[w * 2 + tid];
            r = fminf(fmaxf(r, 0.0f), 1.0f);
            out[(size_t)(b0 + tid) * T_ + TT] = r;
        }
    };

    for (int tb = 0; tb < T_; tb += 2) {
        step(0, 1, tb);
        step(1, 0, tb + 1);
    }
}

// ---------------- launch ----------------
extern "C" void kernel_launch(void* const* d_in, const int* in_sizes, int n_in,
                              void* d_out, int out_size) {
    const float* x    = (const float*)d_in[0];
    const float* Wih1 = (const float*)d_in[1];
    const float* Whh1 = (const float*)d_in[2];
    const float* bih1 = (const float*)d_in[3];
    const float* bhh1 = (const float*)d_in[4];
    const float* Wih2 = (const float*)d_in[5];
    const float* Whh2 = (const float*)d_in[6];
    const float* bih2 = (const float*)d_in[7];
    const float* bhh2 = (const float*)d_in[8];
    const float* Wout = (const float*)d_in[9];
    const float* bout = (const float*)d_in[10];
    float* out = (float*)d_out;

    xp_wmma<<<(B_ * T_) / 128, 256>>>(x, Wih1);
    lstm_rec<<<128, 256>>>(Whh1, Wih2, Whh2, bih1, bhh1, bih2, bhh2, Wout, bout, out);
    (void)in_sizes; (void)n_in; (void)out_size;
}